// round 5
// baseline (speedup 1.0000x reference)
#include <cuda_runtime.h>
#include <cuda_bf16.h>

#define NODES 20000
#define INF_  128
#define HD    64
#define NH    2
#define DD    32
#define EDG   320000
#define RREL  5
#define KHOP  3

// ---------------- device scratch (static, no allocation) ----------------
__device__ float g_hops[KHOP + 1][NODES * HD];  // hop 0 = projected feats x
__device__ float g_res[NODES * HD];
__device__ float g_el[NODES * NH];
__device__ float g_er[NODES * NH];
__device__ float g_emax[NODES * NH];
__device__ float g_denom[NODES * NH];
__device__ float g_e[EDG * NH];
__device__ float g_alpha[EDG * NH];
__device__ float g_acc[NODES * HD];
__device__ float g_w[8];

// ---------------- helpers ----------------
__device__ __forceinline__ float wsum(float v) {
    v += __shfl_xor_sync(0xffffffffu, v, 16);
    v += __shfl_xor_sync(0xffffffffu, v, 8);
    v += __shfl_xor_sync(0xffffffffu, v, 4);
    v += __shfl_xor_sync(0xffffffffu, v, 2);
    v += __shfl_xor_sync(0xffffffffu, v, 1);
    return v;
}

__device__ __forceinline__ void atomicMaxF(float* addr, float v) {
    if (v >= 0.f) atomicMax((int*)addr, __float_as_int(v));
    else          atomicMin((unsigned int*)addr, __float_as_uint(v));
}

__device__ __forceinline__ void fma4(float4& acc, float a, const float4 w) {
    acc.x = fmaf(a, w.x, acc.x);
    acc.y = fmaf(a, w.y, acc.y);
    acc.z = fmaf(a, w.z, acc.z);
    acc.w = fmaf(a, w.w, acc.w);
}

// ---------------- kernels ----------------

// weights[r] = sum_j w_rel[r,j] + b_rel[r]
__global__ void calc_weights(const float* __restrict__ w_rel, const float* __restrict__ b_rel) {
    int r = threadIdx.x;
    if (r < RREL) {
        float s = b_rel[r];
#pragma unroll
        for (int j = 0; j < RREL; j++) s += w_rel[r * RREL + j];
        g_w[r] = s;
    }
}

// out[N,64] = A[N,128] @ W[128,64].  32 rows/block, thread = 2 rows x 4 cols.
__global__ void gemm_nk128_m64(const float* __restrict__ A, const float* __restrict__ W,
                               float* __restrict__ out) {
    int tx = threadIdx.x & 15;   // col group: cols 4*tx..4*tx+3
    int ty = threadIdx.x >> 4;   // 0..15 -> rows 2*ty, 2*ty+1
    int row0 = blockIdx.x * 32 + ty * 2;   // N=20000 divisible by 32 -> exact
    const float4* A4 = reinterpret_cast<const float4*>(A);
    const float4* W4 = reinterpret_cast<const float4*>(W);
    float4 acc0 = {0, 0, 0, 0}, acc1 = {0, 0, 0, 0};
    int a0 = row0 * 32, a1 = a0 + 32;
#pragma unroll 8
    for (int kk = 0; kk < 32; kk++) {
        float4 ha = A4[a0 + kk];
        float4 hb = A4[a1 + kk];
        float4 w0 = W4[(4 * kk + 0) * 16 + tx];
        float4 w1 = W4[(4 * kk + 1) * 16 + tx];
        float4 w2 = W4[(4 * kk + 2) * 16 + tx];
        float4 w3 = W4[(4 * kk + 3) * 16 + tx];
        fma4(acc0, ha.x, w0); fma4(acc0, ha.y, w1); fma4(acc0, ha.z, w2); fma4(acc0, ha.w, w3);
        fma4(acc1, hb.x, w0); fma4(acc1, hb.y, w1); fma4(acc1, hb.z, w2); fma4(acc1, hb.w, w3);
    }
    float4* O4 = reinterpret_cast<float4*>(out);
    O4[row0 * 16 + tx] = acc0;
    O4[(row0 + 1) * 16 + tx] = acc1;
}

// el/er per (node, head) from x = g_hops[0]
__global__ void attn_scores(const float* __restrict__ al, const float* __restrict__ ar) {
    int t = blockIdx.x * blockDim.x + threadIdx.x;
    if (t >= NODES * NH) return;
    int n = t >> 1, hh = t & 1;
    const float4* xv = reinterpret_cast<const float4*>(&g_hops[0][(n << 6) + (hh << 5)]);
    const float4* a4 = reinterpret_cast<const float4*>(al + hh * DD);
    const float4* b4 = reinterpret_cast<const float4*>(ar + hh * DD);
    float sl = 0.f, sr = 0.f;
#pragma unroll
    for (int i = 0; i < 8; i++) {
        float4 x = xv[i], a = a4[i], b = b4[i];
        sl += x.x * a.x + x.y * a.y + x.z * a.z + x.w * a.w;
        sr += x.x * b.x + x.y * b.y + x.z * b.z + x.w * b.w;
    }
    g_el[t] = sl;
    g_er[t] = sr;
}

__global__ void init_softmax() {
    int t = blockIdx.x * blockDim.x + threadIdx.x;
    if (t >= NODES * NH) return;
    g_emax[t] = __int_as_float(0xff800000);  // -inf
    g_denom[t] = 0.f;
}

__global__ void edge_logits(const int* __restrict__ src, const int* __restrict__ dst) {
    int t = blockIdx.x * blockDim.x + threadIdx.x;  // E*NH, exact
    int e = t >> 1, hh = t & 1;
    int s = src[e], d = dst[e];
    float v = g_el[s * 2 + hh] + g_er[d * 2 + hh];
    v = v > 0.f ? v : 0.2f * v;
    g_e[t] = v;
    atomicMaxF(&g_emax[d * 2 + hh], v);
}

__global__ void edge_exp(const int* __restrict__ dst) {
    int t = blockIdx.x * blockDim.x + threadIdx.x;
    int e = t >> 1, hh = t & 1;
    int d = dst[e];
    float ee = __expf(g_e[t] - g_emax[d * 2 + hh]);
    g_alpha[t] = ee;
    atomicAdd(&g_denom[d * 2 + hh], ee);
}

__global__ void edge_div(const int* __restrict__ dst) {
    int t = blockIdx.x * blockDim.x + threadIdx.x;
    int e = t >> 1, hh = t & 1;
    int d = dst[e];
    g_alpha[t] = g_alpha[t] / fmaxf(g_denom[d * 2 + hh], 1e-9f);
}

// one diffusion hop: hout[dst] += alpha * hin[src]   (thread per edge-feature)
__global__ void hop_pass(const int* __restrict__ src, const int* __restrict__ dst,
                         const float* __restrict__ hin, float* __restrict__ hout) {
    int t = blockIdx.x * blockDim.x + threadIdx.x;  // E*64, exact
    int e = t >> 6, f = t & 63, hh = f >> 5;
    int s = src[e], d = dst[e];
    float a = g_alpha[e * 2 + hh];
    atomicAdd(&hout[d * 64 + f], a * hin[s * 64 + f]);
}

// per-(n,h) warp: hop L2-norm, hop attention softmax, mix, residual, relation accumulate
__global__ void hop_mix(const float* __restrict__ hal, const float* __restrict__ har, int r) {
    int gt = blockIdx.x * blockDim.x + threadIdx.x;
    int w = gt >> 5, lane = gt & 31;
    if (w >= NODES * NH) return;
    int n = w >> 1, hh = w & 1;
    int base = (n << 6) + (hh << 5) + lane;
    float a_l = hal[hh * DD + lane];
    float a_r = har[hh * DD + lane];
    float nh[KHOP + 1], lg[KHOP + 1];
#pragma unroll
    for (int k = 0; k < KHOP + 1; k++) {
        float v = g_hops[k][base];
        float ss = wsum(v * v);
        float sc = 1.f / fmaxf(sqrtf(ss), 1e-9f);
        nh[k] = v * sc;
        lg[k] = wsum(nh[k] * a_l);
    }
    float hr = wsum(nh[0] * a_r);
    float m = -1e30f;
#pragma unroll
    for (int k = 0; k < KHOP + 1; k++) {
        float x = lg[k] + hr;
        lg[k] = x > 0.f ? x : 0.2f * x;
        m = fmaxf(m, lg[k]);
    }
    float s = 0.f, wk[KHOP + 1];
#pragma unroll
    for (int k = 0; k < KHOP + 1; k++) { wk[k] = __expf(lg[k] - m); s += wk[k]; }
    float inv = 1.f / s;
    float mix = 0.f;
#pragma unroll
    for (int k = 0; k < KHOP + 1; k++) mix = fmaf(wk[k] * inv, nh[k], mix);
    g_acc[base] += g_w[r] * (mix + g_res[base]);
}

// mean over heads -> [N, 32]
__global__ void final_combine(float* __restrict__ out) {
    int t = blockIdx.x * blockDim.x + threadIdx.x;  // N*32, exact
    int n = t >> 5, d = t & 31;
    out[t] = 0.5f * (g_acc[(n << 6) + d] + g_acc[(n << 6) + 32 + d]);
}

// ---------------- launch ----------------
extern "C" void kernel_launch(void* const* d_in, const int* in_sizes, int n_in,
                              void* d_out, int out_size) {
    const float* h    = (const float*)d_in[0];
    const int*   src  = (const int*)d_in[1];
    const int*   dst  = (const int*)d_in[2];
    const float* fcw  = (const float*)d_in[3];
    const float* rsw  = (const float*)d_in[4];
    const float* al   = (const float*)d_in[5];
    const float* ar   = (const float*)d_in[6];
    const float* hal  = (const float*)d_in[7];
    const float* har  = (const float*)d_in[8];
    const float* wrel = (const float*)d_in[9];
    const float* brel = (const float*)d_in[10];
    float* out = (float*)d_out;

    void *hops_p = nullptr, *acc_p = nullptr, *res_p = nullptr;
    cudaGetSymbolAddress(&hops_p, g_hops);
    cudaGetSymbolAddress(&acc_p, g_acc);
    cudaGetSymbolAddress(&res_p, g_res);
    float* hopsPtr = (float*)hops_p;

    const size_t hopBytes = (size_t)NODES * HD * sizeof(float);

    cudaMemsetAsync(acc_p, 0, hopBytes, 0);
    calc_weights<<<1, 32>>>(wrel, brel);

    const int nhBlocks   = (NODES * NH + 255) / 256;      // 157
    const int edgeBlocks = (EDG * NH) / 256;              // 2500 exact
    const int hopBlocks  = (EDG * HD) / 256;              // 80000 exact
    const int mixBlocks  = (NODES * NH * 32) / 256;       // 5000 exact

    for (int r = 0; r < RREL; r++) {
        const int* sr_ = src + (size_t)r * EDG;
        const int* ds_ = dst + (size_t)r * EDG;

        gemm_nk128_m64<<<NODES / 32, 256>>>(h, fcw + (size_t)r * INF_ * HD, hopsPtr);
        gemm_nk128_m64<<<NODES / 32, 256>>>(h, rsw + (size_t)r * INF_ * HD, (float*)res_p);

        attn_scores<<<nhBlocks, 256>>>(al + r * NH * DD, ar + r * NH * DD);
        init_softmax<<<nhBlocks, 256>>>();

        edge_logits<<<edgeBlocks, 256>>>(sr_, ds_);
        edge_exp<<<edgeBlocks, 256>>>(ds_);
        edge_div<<<edgeBlocks, 256>>>(ds_);

        for (int k = 0; k < KHOP; k++) {
            cudaMemsetAsync(hopsPtr + (size_t)(k + 1) * NODES * HD, 0, hopBytes, 0);
            hop_pass<<<hopBlocks, 256>>>(sr_, ds_,
                                         hopsPtr + (size_t)k * NODES * HD,
                                         hopsPtr + (size_t)(k + 1) * NODES * HD);
        }

        hop_mix<<<mixBlocks, 256>>>(hal + r * NH * DD, har + r * NH * DD, r);
    }

    final_combine<<<(NODES * DD) / 256, 256>>>(out);
}

// round 6
// speedup vs baseline: 2.3468x; 2.3468x over previous
#include <cuda_runtime.h>
#include <cuda_bf16.h>

#define NODES 20000
#define INF_  128
#define HD    64
#define NH    2
#define DD    32
#define EDG   320000
#define RREL  5
#define KHOP  3

// ---------------- device scratch (static, no allocation) ----------------
__device__ float g_x[RREL][NODES * HD];               // hop-0 projected feats per relation
__device__ float g_hops[KHOP][RREL][NODES * HD];      // hops 1..K
__device__ float g_acc[NODES * HD];                   // running output accumulator
__device__ float g_el[RREL][NODES * NH];
__device__ float g_er[RREL][NODES * NH];
__device__ float g_alpha[RREL][EDG * NH];             // softmax alpha in CSR order
__device__ int   g_csr_src[RREL][EDG];                // src ids grouped by dst
__device__ int   g_deg[RREL * NODES];
__device__ int   g_off[RREL][NODES + 1];
__device__ int   g_cur[RREL * NODES];
__device__ float g_w[8];
__device__ float g_wres[INF_ * HD];                   // sum_r w_r * res_w[r]

// ---------------- helpers ----------------
__device__ __forceinline__ float wsum(float v) {
    v += __shfl_xor_sync(0xffffffffu, v, 16);
    v += __shfl_xor_sync(0xffffffffu, v, 8);
    v += __shfl_xor_sync(0xffffffffu, v, 4);
    v += __shfl_xor_sync(0xffffffffu, v, 2);
    v += __shfl_xor_sync(0xffffffffu, v, 1);
    return v;
}
__device__ __forceinline__ float wmax(float v) {
    v = fmaxf(v, __shfl_xor_sync(0xffffffffu, v, 16));
    v = fmaxf(v, __shfl_xor_sync(0xffffffffu, v, 8));
    v = fmaxf(v, __shfl_xor_sync(0xffffffffu, v, 4));
    v = fmaxf(v, __shfl_xor_sync(0xffffffffu, v, 2));
    v = fmaxf(v, __shfl_xor_sync(0xffffffffu, v, 1));
    return v;
}
__device__ __forceinline__ void fma4(float4& acc, float a, const float4 w) {
    acc.x = fmaf(a, w.x, acc.x);
    acc.y = fmaf(a, w.y, acc.y);
    acc.z = fmaf(a, w.z, acc.z);
    acc.w = fmaf(a, w.w, acc.w);
}

// ---------------- small setup kernels ----------------
__global__ void calc_weights(const float* __restrict__ w_rel, const float* __restrict__ b_rel) {
    int r = threadIdx.x;
    if (r < RREL) {
        float s = b_rel[r];
#pragma unroll
        for (int j = 0; j < RREL; j++) s += w_rel[r * RREL + j];
        g_w[r] = s;
    }
}

__global__ void combine_res_w(const float* __restrict__ rsw) {
    int i = blockIdx.x * blockDim.x + threadIdx.x;   // INF_*HD = 8192 exact
    float s = 0.f;
#pragma unroll
    for (int r = 0; r < RREL; r++) s = fmaf(g_w[r], rsw[r * INF_ * HD + i], s);
    g_wres[i] = s;
}

// ---------------- CSR build (all relations) ----------------
__global__ void csr_count(const int* __restrict__ dst) {
    int t = blockIdx.x * blockDim.x + threadIdx.x;   // RREL*EDG exact
    int r = t / EDG;
    atomicAdd(&g_deg[r * NODES + dst[t]], 1);
}

__global__ void csr_scan() {                          // one block per relation
    int r = blockIdx.x;
    __shared__ int part[1024];
    int t = threadIdx.x;
    int base = t * 20;
    int local[20];
    int s = 0;
#pragma unroll
    for (int i = 0; i < 20; i++) {
        int idx = base + i;
        local[i] = s;
        if (idx < NODES) s += g_deg[r * NODES + idx];
    }
    part[t] = s;
    __syncthreads();
    for (int off = 1; off < 1024; off <<= 1) {
        int v = (t >= off) ? part[t - off] : 0;
        __syncthreads();
        part[t] += v;
        __syncthreads();
    }
    int pre = (t == 0) ? 0 : part[t - 1];
#pragma unroll
    for (int i = 0; i < 20; i++) {
        int idx = base + i;
        if (idx < NODES) {
            g_off[r][idx] = pre + local[i];
            g_cur[r * NODES + idx] = 0;
        }
    }
    if (t == 1023) g_off[r][NODES] = EDG;
}

__global__ void csr_fill(const int* __restrict__ src, const int* __restrict__ dst) {
    int t = blockIdx.x * blockDim.x + threadIdx.x;   // RREL*EDG exact
    int r = t / EDG;
    int d = dst[t];
    int pos = g_off[r][d] + atomicAdd(&g_cur[r * NODES + d], 1);
    g_csr_src[r][pos] = src[t];
}

// ---------------- GEMMs: out[N,64] = A[N,128] @ W[128,64] ----------------
__device__ __forceinline__ void gemm_body(const float* __restrict__ A,
                                          const float* __restrict__ W,
                                          float* __restrict__ out) {
    int tx = threadIdx.x & 15;
    int ty = threadIdx.x >> 4;
    int row0 = blockIdx.x * 32 + ty * 2;
    const float4* A4 = reinterpret_cast<const float4*>(A);
    const float4* W4 = reinterpret_cast<const float4*>(W);
    float4 acc0 = {0, 0, 0, 0}, acc1 = {0, 0, 0, 0};
    int a0 = row0 * 32, a1 = a0 + 32;
#pragma unroll 8
    for (int kk = 0; kk < 32; kk++) {
        float4 ha = A4[a0 + kk];
        float4 hb = A4[a1 + kk];
        float4 w0 = W4[(4 * kk + 0) * 16 + tx];
        float4 w1 = W4[(4 * kk + 1) * 16 + tx];
        float4 w2 = W4[(4 * kk + 2) * 16 + tx];
        float4 w3 = W4[(4 * kk + 3) * 16 + tx];
        fma4(acc0, ha.x, w0); fma4(acc0, ha.y, w1); fma4(acc0, ha.z, w2); fma4(acc0, ha.w, w3);
        fma4(acc1, hb.x, w0); fma4(acc1, hb.y, w1); fma4(acc1, hb.z, w2); fma4(acc1, hb.w, w3);
    }
    float4* O4 = reinterpret_cast<float4*>(out);
    O4[row0 * 16 + tx] = acc0;
    O4[(row0 + 1) * 16 + tx] = acc1;
}

__global__ void gemm_fc(const float* __restrict__ A, const float* __restrict__ fcw) {
    int r = blockIdx.y;
    gemm_body(A, fcw + (size_t)r * INF_ * HD, g_x[r]);
}

__global__ void gemm_res(const float* __restrict__ A) {
    gemm_body(A, g_wres, g_acc);
}

// ---------------- attention scores (all relations) ----------------
__global__ void attn_scores(const float* __restrict__ al, const float* __restrict__ ar) {
    int t = blockIdx.x * blockDim.x + threadIdx.x;
    if (t >= NODES * NH) return;
    int r = blockIdx.y;
    int n = t >> 1, hh = t & 1;
    const float4* xv = reinterpret_cast<const float4*>(&g_x[r][(n << 6) + (hh << 5)]);
    const float4* a4 = reinterpret_cast<const float4*>(al + r * NH * DD + hh * DD);
    const float4* b4 = reinterpret_cast<const float4*>(ar + r * NH * DD + hh * DD);
    float sl = 0.f, sr = 0.f;
#pragma unroll
    for (int i = 0; i < 8; i++) {
        float4 x = xv[i], a = a4[i], b = b4[i];
        sl += x.x * a.x + x.y * a.y + x.z * a.z + x.w * a.w;
        sr += x.x * b.x + x.y * b.y + x.z * b.z + x.w * b.w;
    }
    g_el[r][t] = sl;
    g_er[r][t] = sr;
}

// ---------------- per-dst softmax over CSR edges (warp per (r,dst)) ----------------
__global__ void csr_softmax() {
    int gt = blockIdx.x * blockDim.x + threadIdx.x;
    int w = gt >> 5, lane = gt & 31;                 // w in [0, RREL*NODES), exact grid
    int r = w / NODES, d = w - r * NODES;
    int off = g_off[r][d], deg = g_off[r][d + 1] - off;
    if (deg == 0) return;
    float er0 = g_er[r][d * 2], er1 = g_er[r][d * 2 + 1];
    float m0 = -1e30f, m1 = -1e30f;
    for (int i = lane; i < deg; i += 32) {
        int s = g_csr_src[r][off + i];
        float l0 = g_el[r][s * 2] + er0;
        float l1 = g_el[r][s * 2 + 1] + er1;
        l0 = l0 > 0.f ? l0 : 0.2f * l0;
        l1 = l1 > 0.f ? l1 : 0.2f * l1;
        g_alpha[r][(off + i) * 2] = l0;
        g_alpha[r][(off + i) * 2 + 1] = l1;
        m0 = fmaxf(m0, l0);
        m1 = fmaxf(m1, l1);
    }
    m0 = wmax(m0); m1 = wmax(m1);
    float s0 = 0.f, s1 = 0.f;
    for (int i = lane; i < deg; i += 32) {
        float e0 = __expf(g_alpha[r][(off + i) * 2] - m0);
        float e1 = __expf(g_alpha[r][(off + i) * 2 + 1] - m1);
        g_alpha[r][(off + i) * 2] = e0;
        g_alpha[r][(off + i) * 2 + 1] = e1;
        s0 += e0; s1 += e1;
    }
    s0 = wsum(s0); s1 = wsum(s1);
    float i0 = 1.f / fmaxf(s0, 1e-9f);
    float i1 = 1.f / fmaxf(s1, 1e-9f);
    for (int i = lane; i < deg; i += 32) {
        g_alpha[r][(off + i) * 2] *= i0;
        g_alpha[r][(off + i) * 2 + 1] *= i1;
    }
}

// ---------------- diffusion hop, gather form (warp per (r,dst)) ----------------
__global__ void hop_gather(int k) {
    int gt = blockIdx.x * blockDim.x + threadIdx.x;
    int w = gt >> 5, lane = gt & 31;                 // w in [0, RREL*NODES), exact grid
    int r = w / NODES, d = w - r * NODES;
    int off = g_off[r][d], deg = g_off[r][d + 1] - off;
    const float* __restrict__ hin = (k == 0) ? g_x[r] : g_hops[k - 1][r];
    float* __restrict__ hout = g_hops[k][r];
    float acc0 = 0.f, acc1 = 0.f;
    for (int c = 0; c < deg; c += 32) {
        int i = c + lane;
        int s = 0; float a0 = 0.f, a1 = 0.f;
        if (i < deg) {
            s = g_csr_src[r][off + i];
            float2 aa = *reinterpret_cast<const float2*>(&g_alpha[r][(off + i) * 2]);
            a0 = aa.x; a1 = aa.y;
        }
        int lim = min(32, deg - c);
#pragma unroll 4
        for (int j = 0; j < lim; j++) {
            int   sj  = __shfl_sync(0xffffffffu, s, j);
            float a0j = __shfl_sync(0xffffffffu, a0, j);
            float a1j = __shfl_sync(0xffffffffu, a1, j);
            const float* row = hin + (sj << 6);
            acc0 = fmaf(a0j, row[lane], acc0);
            acc1 = fmaf(a1j, row[32 + lane], acc1);
        }
    }
    hout[(d << 6) + lane] = acc0;
    hout[(d << 6) + 32 + lane] = acc1;
}

// ---------------- hop attention + mix + relation-weighted accumulate ----------------
__global__ void hop_mix(const float* __restrict__ hal, const float* __restrict__ har) {
    int gt = blockIdx.x * blockDim.x + threadIdx.x;
    int w = gt >> 5, lane = gt & 31;                 // w in [0, NODES*NH), exact grid
    int n = w >> 1, hh = w & 1;
    int base = (n << 6) + (hh << 5) + lane;
    float accv = g_acc[base];                        // residual already here
#pragma unroll
    for (int r = 0; r < RREL; r++) {
        float a_l = hal[r * HD + hh * DD + lane];
        float a_r = har[r * HD + hh * DD + lane];
        float nh[KHOP + 1], lg[KHOP + 1];
#pragma unroll
        for (int k = 0; k < KHOP + 1; k++) {
            float v = (k == 0) ? g_x[r][base] : g_hops[k - 1][r][base];
            float ss = wsum(v * v);
            float sc = 1.f / fmaxf(sqrtf(ss), 1e-9f);
            nh[k] = v * sc;
            lg[k] = wsum(nh[k] * a_l);
        }
        float hr = wsum(nh[0] * a_r);
        float m = -1e30f;
#pragma unroll
        for (int k = 0; k < KHOP + 1; k++) {
            float x = lg[k] + hr;
            lg[k] = x > 0.f ? x : 0.2f * x;
            m = fmaxf(m, lg[k]);
        }
        float s = 0.f, wk[KHOP + 1];
#pragma unroll
        for (int k = 0; k < KHOP + 1; k++) { wk[k] = __expf(lg[k] - m); s += wk[k]; }
        float inv = 1.f / s;
        float mix = 0.f;
#pragma unroll
        for (int k = 0; k < KHOP + 1; k++) mix = fmaf(wk[k] * inv, nh[k], mix);
        accv = fmaf(g_w[r], mix, accv);
    }
    g_acc[base] = accv;
}

// ---------------- mean over heads -> [N, 32] ----------------
__global__ void final_combine(float* __restrict__ out) {
    int t = blockIdx.x * blockDim.x + threadIdx.x;   // NODES*DD exact
    int n = t >> 5, d = t & 31;
    out[t] = 0.5f * (g_acc[(n << 6) + d] + g_acc[(n << 6) + 32 + d]);
}

// ---------------- launch ----------------
extern "C" void kernel_launch(void* const* d_in, const int* in_sizes, int n_in,
                              void* d_out, int out_size) {
    const float* h    = (const float*)d_in[0];
    const int*   src  = (const int*)d_in[1];
    const int*   dst  = (const int*)d_in[2];
    const float* fcw  = (const float*)d_in[3];
    const float* rsw  = (const float*)d_in[4];
    const float* al   = (const float*)d_in[5];
    const float* ar   = (const float*)d_in[6];
    const float* hal  = (const float*)d_in[7];
    const float* har  = (const float*)d_in[8];
    const float* wrel = (const float*)d_in[9];
    const float* brel = (const float*)d_in[10];
    float* out = (float*)d_out;

    void* deg_p = nullptr;
    cudaGetSymbolAddress(&deg_p, g_deg);

    // setup
    calc_weights<<<1, 32>>>(wrel, brel);
    combine_res_w<<<(INF_ * HD) / 256, 256>>>(rsw);
    cudaMemsetAsync(deg_p, 0, (size_t)RREL * NODES * sizeof(int), 0);

    // CSR build (all relations at once)
    const int reBlocks = (RREL * EDG) / 256;                 // 6250 exact
    csr_count<<<reBlocks, 256>>>(dst);
    csr_scan<<<RREL, 1024>>>();
    csr_fill<<<reBlocks, 256>>>(src, dst);

    // GEMMs: 5 fc projections + 1 combined residual
    dim3 gf(NODES / 32, RREL);
    gemm_fc<<<gf, 256>>>(h, fcw);
    gemm_res<<<NODES / 32, 256>>>(h);

    // attention scores for all relations
    dim3 ga((NODES * NH + 255) / 256, RREL);
    attn_scores<<<ga, 256>>>(al, ar);

    // per-dst softmax, all relations (warp per (r,d))
    const int wBlocks = (RREL * NODES * 32) / 256;           // 12500 exact
    csr_softmax<<<wBlocks, 256>>>();

    // K diffusion hops, all relations per launch
    for (int k = 0; k < KHOP; k++)
        hop_gather<<<wBlocks, 256>>>(k);

    // hop attention + mix + accumulate over relations
    hop_mix<<<(NODES * NH * 32) / 256, 256>>>(hal, har);

    final_combine<<<(NODES * DD) / 256, 256>>>(out);
}